// round 15
// baseline (speedup 1.0000x reference)
#include <cuda_runtime.h>
#include <cuda_bf16.h>
#include <cuda_fp8.h>
#include <stdint.h>

// Problem dims
#define MQ    8192
#define DD    1024
#define NC    16384
#define KSEL  8
#define NCAND 128

// FP8 shortlist tiling: 64 queries x 128-code chunks, warp tile 32x32,
// K-slab = 64 fp8 bytes, flattened slab pipeline (depth 3), occupancy 2.
#define BM 64
#define BN 128
#define NT 256
#define NSPLIT 4
#define CODES_PER_CTA (NC / NSPLIT)      // 4096
#define NCHUNK (CODES_PER_CTA / BN)      // 32
#define NKT    16                        // 1024 / 64
#define TOTSLAB (NCHUNK * NKT)           // 512

#define ROWB   80u                       // 64 data bytes + 16 pad
#define A_BYTES (64u * ROWB)             // 5120
#define B_BYTES (128u * ROWB)            // 10240
#define STAGE_BYTES (A_BYTES + B_BYTES)  // 15360
#define NSTAGE 4
#define STG_OFF (NSTAGE * STAGE_BYTES)   // 61440
#define SMEM_BYTES (STG_OFF + BM * BN * 4)  // 61440 + 32768 = 94208

// ---------------------------------------------------------------------------
__device__ float    g_c2[NC];
__device__ float    g_x2[MQ];
__device__ uint8_t  g_X8[(size_t)MQ * DD];   // e4m3 queries  (8 MB)
__device__ uint8_t  g_C8[(size_t)NC * DD];   // e4m3 codebook (16 MB)
__device__ int      g_cand[(size_t)MQ * NCAND];

// ---------------------------------------------------------------------------
// Fused convert(e4m3) + squared-norm kernels: one warp per row, single pass.
__device__ __forceinline__ uint32_t pack_fp8x4(float4 v) {
    uint32_t b0 = __nv_cvt_float_to_fp8(v.x, __NV_SATFINITE, __NV_E4M3);
    uint32_t b1 = __nv_cvt_float_to_fp8(v.y, __NV_SATFINITE, __NV_E4M3);
    uint32_t b2 = __nv_cvt_float_to_fp8(v.z, __NV_SATFINITE, __NV_E4M3);
    uint32_t b3 = __nv_cvt_float_to_fp8(v.w, __NV_SATFINITE, __NV_E4M3);
    return b0 | (b1 << 8) | (b2 << 16) | (b3 << 24);
}

__global__ void cprep_kernel(const float* __restrict__ src) {
    int row = blockIdx.x * 8 + (threadIdx.x >> 5);
    if (row >= NC) return;
    int lane = threadIdx.x & 31;
    const float4* r4 = (const float4*)(src + (size_t)row * DD);
    uint32_t* dst = (uint32_t*)(g_C8 + (size_t)row * DD);
    float s = 0.f;
#pragma unroll
    for (int i = 0; i < 8; ++i) {
        float4 v = r4[i * 32 + lane];
        s += v.x * v.x + v.y * v.y + v.z * v.z + v.w * v.w;
        dst[i * 32 + lane] = pack_fp8x4(v);
    }
#pragma unroll
    for (int o = 16; o > 0; o >>= 1) s += __shfl_xor_sync(0xffffffffu, s, o);
    if (lane == 0) g_c2[row] = s;
}

__global__ void xprep_kernel(const float* __restrict__ src) {
    int row = blockIdx.x * 8 + (threadIdx.x >> 5);
    if (row >= MQ) return;
    int lane = threadIdx.x & 31;
    const float4* r4 = (const float4*)(src + (size_t)row * DD);
    uint32_t* dst = (uint32_t*)(g_X8 + (size_t)row * DD);
    float s = 0.f;
#pragma unroll
    for (int i = 0; i < 8; ++i) {
        float4 v = r4[i * 32 + lane];
        s += v.x * v.x + v.y * v.y + v.z * v.z + v.w * v.w;
        dst[i * 32 + lane] = pack_fp8x4(v);
    }
#pragma unroll
    for (int o = 16; o > 0; o >>= 1) s += __shfl_xor_sync(0xffffffffu, s, o);
    if (lane == 0) g_x2[row] = s;
}

// ---------------------------------------------------------------------------
// Scalar top-8 (value desc; ties -> smaller index first, matching JAX top_k)
#define BUBBLE(va, ia, vb, ib)                                    \
    if (va > vb || (va == vb && ia < ib)) {                       \
        float _tv = va; va = vb; vb = _tv;                        \
        int   _ti = ia; ia = ib; ib = _ti;                        \
    }
#define TRYINS(s, n)                                              \
    if ((s) > v7 || ((s) == v7 && (n) < j7)) {                    \
        v7 = (s); j7 = (n);                                       \
        BUBBLE(v7, j7, v6, j6)                                    \
        BUBBLE(v6, j6, v5, j5)                                    \
        BUBBLE(v5, j5, v4, j4)                                    \
        BUBBLE(v4, j4, v3, j3)                                    \
        BUBBLE(v3, j3, v2, j2)                                    \
        BUBBLE(v2, j2, v1, j1)                                    \
        BUBBLE(v1, j1, v0, j0)                                    \
    }

// ---------------------------------------------------------------------------
// PTX wrappers
__device__ __forceinline__ void ldsm_x4(uint32_t* r, uint32_t addr) {
    asm volatile("ldmatrix.sync.aligned.m8n8.x4.shared.b16 {%0,%1,%2,%3}, [%4];\n"
        : "=r"(r[0]), "=r"(r[1]), "=r"(r[2]), "=r"(r[3]) : "r"(addr));
}
__device__ __forceinline__ void mma_fp8(float* d, const uint32_t* a, const uint32_t* b) {
    asm volatile("mma.sync.aligned.m16n8k32.row.col.f32.e4m3.e4m3.f32 "
        "{%0,%1,%2,%3}, {%4,%5,%6,%7}, {%8,%9}, {%0,%1,%2,%3};\n"
        : "+f"(d[0]), "+f"(d[1]), "+f"(d[2]), "+f"(d[3])
        : "r"(a[0]), "r"(a[1]), "r"(a[2]), "r"(a[3]), "r"(b[0]), "r"(b[1]));
}
#define CPA(dst, src) \
    asm volatile("cp.async.cg.shared.global [%0], [%1], 16;\n" :: "r"(dst), "l"(src))
#define CP_COMMIT asm volatile("cp.async.commit_group;\n" ::)
#define CP_WAIT2  asm volatile("cp.async.wait_group 2;\n" ::)
#define CP_WAIT1  asm volatile("cp.async.wait_group 1;\n" ::)
#define CP_WAIT0  asm volatile("cp.async.wait_group 0;\n" ::)

// ---------------------------------------------------------------------------
// Shortlist kernel: e4m3 mma.sync GEMM (score = 2*xc - c2) + per-thread top-8.
// Flattened slab pipeline, prefetch depth 3 (NSTAGE=4, wait_group 2).
__global__ void __launch_bounds__(NT, 2) shortlist_kernel() {
    extern __shared__ __align__(128) unsigned char sraw[];
    float* Stg = (float*)(sraw + STG_OFF);

    const int tid  = threadIdx.x;
    const int lane = tid & 31;
    const int wid  = tid >> 5;
    const int wm   = (wid >> 2) * 32;               // warp m-origin: 0,32
    const int wn   = (wid & 3) * 32;                // warp n-origin: 0,32,64,96
    const int gid  = lane >> 2;
    const int tig  = lane & 3;
    const int mBase = blockIdx.x * BM;
    const int cBase = blockIdx.y * CODES_PER_CTA;

    const uint32_t sBase = (uint32_t)__cvta_generic_to_shared(sraw);

    // cp.async decomposition: A 64 rows x 4 segs (1/thread), B 128 rows x 4 segs (2/thread)
    const int a_row = tid >> 2, a_seg = tid & 3;
    const int b_row = tid >> 1, b_seg = (tid & 1) * 2;
    const uint8_t* aSrc = g_X8 + (size_t)(mBase + a_row) * DD + a_seg * 16;
    const uint8_t* bBase = g_C8 + (size_t)(cBase + b_row) * DD + b_seg * 16;
    const uint32_t aDst = sBase + (uint32_t)a_row * ROWB + a_seg * 16;
    const uint32_t bDst = sBase + A_BYTES + (uint32_t)b_row * ROWB + b_seg * 16;

    // ldmatrix lane->address maps (byte units; rows are 80B apart)
    const int aLdRow = lane & 15;
    const int aLdCol = 16 * (lane >> 4);
    const int bLdRow = (lane & 7) + ((lane >> 4) << 3);
    const int bLdCol = 16 * ((lane >> 3) & 1);

    const float NEG_INF = __int_as_float(0xff800000);
    float v0 = NEG_INF, v1 = NEG_INF, v2 = NEG_INF, v3 = NEG_INF;
    float v4 = NEG_INF, v5 = NEG_INF, v6 = NEG_INF, v7 = NEG_INF;
    int j0 = 0x7FFFFFFF, j1 = 0x7FFFFFFF, j2 = 0x7FFFFFFF, j3 = 0x7FFFFFFF;
    int j4 = 0x7FFFFFFF, j5 = 0x7FFFFFFF, j6 = 0x7FFFFFFF, j7 = 0x7FFFFFFF;

    const int q_scan = tid >> 2;                    // query row (0..63)
    const int l4     = tid & 3;                     // 32-col slice
    const int rot    = (q_scan + l4 * 8) & 31;

    // PF: prefetch slab G (chunk G/NKT, kt G%NKT) into buf G%NSTAGE.
#define PF(G)                                                                 \
    do {                                                                      \
        uint32_t so = (uint32_t)((G) % NSTAGE) * STAGE_BYTES;                 \
        const uint8_t* as = aSrc + ((G) & (NKT - 1)) * 64;                    \
        const uint8_t* bs = bBase + (size_t)((G) >> 4) * (BN * DD)            \
                            + ((G) & (NKT - 1)) * 64;                        \
        CPA(aDst + so, as);                                                   \
        CPA(bDst + so, bs);                                                   \
        CPA(bDst + so + 16u, bs + 16);                                        \
        CP_COMMIT;                                                            \
    } while (0)

    PF(0);
    PF(1);
    PF(2);

    float ac[2][4][4];
#pragma unroll
    for (int ma = 0; ma < 2; ++ma)
#pragma unroll
        for (int nb = 0; nb < 4; ++nb)
#pragma unroll
            for (int r = 0; r < 4; ++r) ac[ma][nb][r] = 0.f;

#pragma unroll 1
    for (int g = 0; g < TOTSLAB; ++g) {
        if (g < TOTSLAB - 2)      { CP_WAIT2; }
        else if (g == TOTSLAB - 2){ CP_WAIT1; }
        else                      { CP_WAIT0; }
        __syncthreads();                 // slab g ready; buf (g+3)%4 consumed
        if (g + 3 < TOTSLAB) PF(g + 3);

        const uint32_t sA = sBase + (uint32_t)(g % NSTAGE) * STAGE_BYTES;
        const uint32_t sB = sA + A_BYTES;
#pragma unroll
        for (int ks = 0; ks < 2; ++ks) {          // two k32 steps per 64B slab
            const int k0 = ks * 32;
            uint32_t af[2][4], bf[4][2];
#pragma unroll
            for (int ma = 0; ma < 2; ++ma)
                ldsm_x4(af[ma],
                        sA + (uint32_t)(wm + ma * 16 + aLdRow) * ROWB + k0 + aLdCol);
#pragma unroll
            for (int nq = 0; nq < 2; ++nq) {
                uint32_t t[4];
                ldsm_x4(t, sB + (uint32_t)(wn + nq * 16 + bLdRow) * ROWB + k0 + bLdCol);
                bf[nq * 2][0] = t[0]; bf[nq * 2][1] = t[1];
                bf[nq * 2 + 1][0] = t[2]; bf[nq * 2 + 1][1] = t[3];
            }
#pragma unroll
            for (int ma = 0; ma < 2; ++ma)
#pragma unroll
                for (int nb = 0; nb < 4; ++nb)
                    mma_fp8(ac[ma][nb], af[ma], bf[nb]);
        }

        if ((g & (NKT - 1)) == NKT - 1) {
            // ---- chunk epilogue (pipeline stays full)
            const int nBase = (g >> 4) * BN;

            // Stage scores psi = 2*dot - c2 into Stg.
#pragma unroll
            for (int ma = 0; ma < 2; ++ma) {
                const int m0 = wm + ma * 16 + gid;
#pragma unroll
                for (int nb = 0; nb < 4; ++nb) {
                    const int n0 = wn + nb * 8 + 2 * tig;
                    const float cc0 = g_c2[cBase + nBase + n0];
                    const float cc1 = g_c2[cBase + nBase + n0 + 1];
                    Stg[m0 * BN + n0]           = fmaf(2.f, ac[ma][nb][0], -cc0);
                    Stg[m0 * BN + n0 + 1]       = fmaf(2.f, ac[ma][nb][1], -cc1);
                    Stg[(m0 + 8) * BN + n0]     = fmaf(2.f, ac[ma][nb][2], -cc0);
                    Stg[(m0 + 8) * BN + n0 + 1] = fmaf(2.f, ac[ma][nb][3], -cc1);
                }
            }
            __syncthreads();

            // Top-8 scan: 4 threads per query, 32 cols each (rotated).
            // (No trailing sync: next write to Stg is 16 slabs away, behind
            // multiple __syncthreads.)
#pragma unroll 1
            for (int j = 0; j < 32; ++j) {
                int jj  = (j + rot) & 31;
                int col = l4 * 32 + jj;
                float s = Stg[q_scan * BN + col];
                int   n = cBase + nBase + col;
                TRYINS(s, n)
            }

            // reset accumulators for next chunk
#pragma unroll
            for (int ma = 0; ma < 2; ++ma)
#pragma unroll
                for (int nb = 0; nb < 4; ++nb)
#pragma unroll
                    for (int r = 0; r < 4; ++r) ac[ma][nb][r] = 0.f;
        }
    }
#undef PF

    // Write 32 candidate ids per (query, split): 4 threads x 8 each.
    int* dst = &g_cand[(size_t)(mBase + q_scan) * NCAND + blockIdx.y * 32 + l4 * 8];
    dst[0] = j0; dst[1] = j1; dst[2] = j2; dst[3] = j3;
    dst[4] = j4; dst[5] = j5; dst[6] = j6; dst[7] = j7;
}

// ---------------------------------------------------------------------------
// Exact fp32 rescore: 2 queries per block, 4 warps per query (32 cand each),
// exact top-8 pick (value desc, index asc), gather/mean split across warps.
__global__ void __launch_bounds__(256) rescore_kernel(const float* __restrict__ X,
                                                      const float* __restrict__ C,
                                                      float* __restrict__ out,
                                                      float* __restrict__ out_ids)
{
    __shared__ float sv[2][NCAND];
    __shared__ int   si[2][NCAND];
    __shared__ int   sel[2][KSEL];

    const int tid  = threadIdx.x;
    const int wid  = tid >> 5;
    const int lane = tid & 31;
    const int qw   = wid >> 2;           // query slot in block (0/1)
    const int wq   = wid & 3;            // warp within query (0..3)
    const int q    = blockIdx.x * 2 + qw;

    const float4* X4 = (const float4*)(X + (size_t)q * DD);
    float4 xr[8];
#pragma unroll
    for (int i = 0; i < 8; ++i) xr[i] = X4[i * 32 + lane];
    const float x2 = g_x2[q];

    // 32 candidates per warp
#pragma unroll 1
    for (int cc = 0; cc < NCAND / 4; ++cc) {
        const int c  = wq * (NCAND / 4) + cc;
        const int id = g_cand[(size_t)q * NCAND + c];
        const float4* C4 = (const float4*)(C + (size_t)id * DD);
        float s = 0.f;
#pragma unroll
        for (int i = 0; i < 8; ++i) {
            float4 cv = C4[i * 32 + lane];
            s += xr[i].x * cv.x + xr[i].y * cv.y + xr[i].z * cv.z + xr[i].w * cv.w;
        }
#pragma unroll
        for (int o = 16; o > 0; o >>= 1) s += __shfl_xor_sync(0xffffffffu, s, o);
        if (lane == 0) {
            sv[qw][c] = -(fmaf(-2.f, s, x2) + g_c2[id]);   // reference formula order
            si[qw][c] = id;
        }
    }
    __syncthreads();

    if (wq == 0 && lane == 0) {
        const float NEG_INF = __int_as_float(0xff800000);
        float v0 = NEG_INF, v1 = NEG_INF, v2 = NEG_INF, v3 = NEG_INF;
        float v4 = NEG_INF, v5 = NEG_INF, v6 = NEG_INF, v7 = NEG_INF;
        int j0 = 0x7FFFFFFF, j1 = 0x7FFFFFFF, j2 = 0x7FFFFFFF, j3 = 0x7FFFFFFF;
        int j4 = 0x7FFFFFFF, j5 = 0x7FFFFFFF, j6 = 0x7FFFFFFF, j7 = 0x7FFFFFFF;
#pragma unroll 1
        for (int c = 0; c < NCAND; ++c) {
            float s = sv[qw][c];
            int   n = si[qw][c];
            TRYINS(s, n)
        }
        sel[qw][0] = j0; sel[qw][1] = j1; sel[qw][2] = j2; sel[qw][3] = j3;
        sel[qw][4] = j4; sel[qw][5] = j5; sel[qw][6] = j6; sel[qw][7] = j7;
        if (out_ids) {
            float* o = out_ids + (size_t)q * KSEL;
            o[0] = (float)j0; o[1] = (float)j1; o[2] = (float)j2; o[3] = (float)j3;
            o[4] = (float)j4; o[5] = (float)j5; o[6] = (float)j6; o[7] = (float)j7;
        }
    }
    __syncthreads();

    // Gather + mean: each warp covers dims [wq*256, wq*256+256) for its query.
    const float4* P0 = (const float4*)(C + (size_t)sel[qw][0] * DD);
    const float4* P1 = (const float4*)(C + (size_t)sel[qw][1] * DD);
    const float4* P2 = (const float4*)(C + (size_t)sel[qw][2] * DD);
    const float4* P3 = (const float4*)(C + (size_t)sel[qw][3] * DD);
    const float4* P4 = (const float4*)(C + (size_t)sel[qw][4] * DD);
    const float4* P5 = (const float4*)(C + (size_t)sel[qw][5] * DD);
    const float4* P6 = (const float4*)(C + (size_t)sel[qw][6] * DD);
    const float4* P7 = (const float4*)(C + (size_t)sel[qw][7] * DD);
    float4* O4 = (float4*)(out + (size_t)q * DD);
#pragma unroll
    for (int i = 0; i < 2; ++i) {
        const int f = wq * 64 + i * 32 + lane;
        float4 a0 = P0[f], a1 = P1[f], a2 = P2[f], a3 = P3[f];
        float4 a4 = P4[f], a5 = P5[f], a6 = P6[f], a7 = P7[f];
        float4 rr;
        rr.x = (a0.x + a1.x + a2.x + a3.x + a4.x + a5.x + a6.x + a7.x) * 0.125f;
        rr.y = (a0.y + a1.y + a2.y + a3.y + a4.y + a5.y + a6.y + a7.y) * 0.125f;
        rr.z = (a0.z + a1.z + a2.z + a3.z + a4.z + a5.z + a6.z + a7.z) * 0.125f;
        rr.w = (a0.w + a1.w + a2.w + a3.w + a4.w + a5.w + a6.w + a7.w) * 0.125f;
        O4[f] = rr;
    }
}

// ---------------------------------------------------------------------------
extern "C" void kernel_launch(void* const* d_in, const int* in_sizes, int n_in,
                              void* d_out, int out_size)
{
    const float* X = (const float*)d_in[0];   // inputs   [4,2048,1024] f32
    const float* C = (const float*)d_in[1];   // codebook [16384,1024] f32

    float* out     = (float*)d_out;
    float* out_ids = nullptr;
    if (out_size >= MQ * DD + MQ * KSEL)
        out_ids = out + (size_t)MQ * DD;

    cprep_kernel<<<NC / 8, 256>>>(C);   // e4m3 convert + c2 norms, one pass
    xprep_kernel<<<MQ / 8, 256>>>(X);   // e4m3 convert + x2 norms, one pass

    cudaFuncSetAttribute(shortlist_kernel,
                         cudaFuncAttributeMaxDynamicSharedMemorySize, SMEM_BYTES);
    dim3 grid(MQ / BM, NSPLIT);
    shortlist_kernel<<<grid, NT, SMEM_BYTES>>>();

    rescore_kernel<<<MQ / 2, 256>>>(X, C, out, out_ids);
}

// round 16
// speedup vs baseline: 1.0831x; 1.0831x over previous
#include <cuda_runtime.h>
#include <cuda_bf16.h>
#include <cuda_fp8.h>
#include <stdint.h>

// Problem dims
#define MQ    8192
#define DD    1024
#define NC    16384
#define KSEL  8
#define KKEEP 6                          // candidates kept per scan-thread
#define NCAND 96                         // 4 splits x 4 threads x 6

// FP8 shortlist tiling: 64 queries x 128-code chunks, warp tile 32x32,
// K-slab = 64 fp8 bytes, flattened slab pipeline (depth 2), occupancy 2.
#define BM 64
#define BN 128
#define NT 256
#define NSPLIT 4
#define CODES_PER_CTA (NC / NSPLIT)      // 4096
#define NCHUNK (CODES_PER_CTA / BN)      // 32
#define NKT    16                        // 1024 / 64
#define TOTSLAB (NCHUNK * NKT)           // 512

#define ROWB   80u                       // 64 data bytes + 16 pad
#define A_BYTES (64u * ROWB)             // 5120
#define B_BYTES (128u * ROWB)            // 10240
#define STAGE_BYTES (A_BYTES + B_BYTES)  // 15360
#define NSTAGE 3
#define STG_OFF (NSTAGE * STAGE_BYTES)   // 46080
#define SMEM_BYTES (STG_OFF + BM * BN * 4)  // 78848

// ---------------------------------------------------------------------------
__device__ float    g_c2[NC];
__device__ float    g_x2[MQ];
__device__ uint8_t  g_X8[(size_t)MQ * DD];   // e4m3 queries  (8 MB)
__device__ uint8_t  g_C8[(size_t)NC * DD];   // e4m3 codebook (16 MB)
__device__ int      g_cand[(size_t)MQ * NCAND];

// ---------------------------------------------------------------------------
// Fused convert(e4m3) + squared-norm kernels: one warp per row, single pass.
__device__ __forceinline__ uint32_t pack_fp8x4(float4 v) {
    uint32_t b0 = __nv_cvt_float_to_fp8(v.x, __NV_SATFINITE, __NV_E4M3);
    uint32_t b1 = __nv_cvt_float_to_fp8(v.y, __NV_SATFINITE, __NV_E4M3);
    uint32_t b2 = __nv_cvt_float_to_fp8(v.z, __NV_SATFINITE, __NV_E4M3);
    uint32_t b3 = __nv_cvt_float_to_fp8(v.w, __NV_SATFINITE, __NV_E4M3);
    return b0 | (b1 << 8) | (b2 << 16) | (b3 << 24);
}

__global__ void cprep_kernel(const float* __restrict__ src) {
    int row = blockIdx.x * 8 + (threadIdx.x >> 5);
    if (row >= NC) return;
    int lane = threadIdx.x & 31;
    const float4* r4 = (const float4*)(src + (size_t)row * DD);
    uint32_t* dst = (uint32_t*)(g_C8 + (size_t)row * DD);
    float s = 0.f;
#pragma unroll
    for (int i = 0; i < 8; ++i) {
        float4 v = r4[i * 32 + lane];
        s += v.x * v.x + v.y * v.y + v.z * v.z + v.w * v.w;
        dst[i * 32 + lane] = pack_fp8x4(v);
    }
#pragma unroll
    for (int o = 16; o > 0; o >>= 1) s += __shfl_xor_sync(0xffffffffu, s, o);
    if (lane == 0) g_c2[row] = s;
}

__global__ void xprep_kernel(const float* __restrict__ src) {
    int row = blockIdx.x * 8 + (threadIdx.x >> 5);
    if (row >= MQ) return;
    int lane = threadIdx.x & 31;
    const float4* r4 = (const float4*)(src + (size_t)row * DD);
    uint32_t* dst = (uint32_t*)(g_X8 + (size_t)row * DD);
    float s = 0.f;
#pragma unroll
    for (int i = 0; i < 8; ++i) {
        float4 v = r4[i * 32 + lane];
        s += v.x * v.x + v.y * v.y + v.z * v.z + v.w * v.w;
        dst[i * 32 + lane] = pack_fp8x4(v);
    }
#pragma unroll
    for (int o = 16; o > 0; o >>= 1) s += __shfl_xor_sync(0xffffffffu, s, o);
    if (lane == 0) g_x2[row] = s;
}

// ---------------------------------------------------------------------------
// Scalar top-8 (value desc; ties -> smaller index first, matching JAX top_k)
#define BUBBLE(va, ia, vb, ib)                                    \
    if (va > vb || (va == vb && ia < ib)) {                       \
        float _tv = va; va = vb; vb = _tv;                        \
        int   _ti = ia; ia = ib; ib = _ti;                        \
    }
#define TRYINS(s, n)                                              \
    if ((s) > v7 || ((s) == v7 && (n) < j7)) {                    \
        v7 = (s); j7 = (n);                                       \
        BUBBLE(v7, j7, v6, j6)                                    \
        BUBBLE(v6, j6, v5, j5)                                    \
        BUBBLE(v5, j5, v4, j4)                                    \
        BUBBLE(v4, j4, v3, j3)                                    \
        BUBBLE(v3, j3, v2, j2)                                    \
        BUBBLE(v2, j2, v1, j1)                                    \
        BUBBLE(v1, j1, v0, j0)                                    \
    }

// ---------------------------------------------------------------------------
// PTX wrappers
__device__ __forceinline__ void ldsm_x4(uint32_t* r, uint32_t addr) {
    asm volatile("ldmatrix.sync.aligned.m8n8.x4.shared.b16 {%0,%1,%2,%3}, [%4];\n"
        : "=r"(r[0]), "=r"(r[1]), "=r"(r[2]), "=r"(r[3]) : "r"(addr));
}
__device__ __forceinline__ void mma_fp8(float* d, const uint32_t* a, const uint32_t* b) {
    asm volatile("mma.sync.aligned.m16n8k32.row.col.f32.e4m3.e4m3.f32 "
        "{%0,%1,%2,%3}, {%4,%5,%6,%7}, {%8,%9}, {%0,%1,%2,%3};\n"
        : "+f"(d[0]), "+f"(d[1]), "+f"(d[2]), "+f"(d[3])
        : "r"(a[0]), "r"(a[1]), "r"(a[2]), "r"(a[3]), "r"(b[0]), "r"(b[1]));
}
#define CPA(dst, src) \
    asm volatile("cp.async.cg.shared.global [%0], [%1], 16;\n" :: "r"(dst), "l"(src))
#define CP_COMMIT asm volatile("cp.async.commit_group;\n" ::)
#define CP_WAIT1  asm volatile("cp.async.wait_group 1;\n" ::)
#define CP_WAIT0  asm volatile("cp.async.wait_group 0;\n" ::)

// ---------------------------------------------------------------------------
// Shortlist kernel: e4m3 mma.sync GEMM (score = 2*xc - c2) + per-thread top-8,
// emitting top-6 per thread. Flattened slab pipeline (depth 2, NSTAGE 3).
__global__ void __launch_bounds__(NT, 2) shortlist_kernel() {
    extern __shared__ __align__(128) unsigned char sraw[];
    float* Stg = (float*)(sraw + STG_OFF);

    const int tid  = threadIdx.x;
    const int lane = tid & 31;
    const int wid  = tid >> 5;
    const int wm   = (wid >> 2) * 32;               // warp m-origin: 0,32
    const int wn   = (wid & 3) * 32;                // warp n-origin: 0,32,64,96
    const int gid  = lane >> 2;
    const int tig  = lane & 3;
    const int mBase = blockIdx.x * BM;
    const int cBase = blockIdx.y * CODES_PER_CTA;

    const uint32_t sBase = (uint32_t)__cvta_generic_to_shared(sraw);

    // cp.async decomposition: A 64 rows x 4 segs (1/thread), B 128 rows x 4 segs (2/thread)
    const int a_row = tid >> 2, a_seg = tid & 3;
    const int b_row = tid >> 1, b_seg = (tid & 1) * 2;
    const uint8_t* aSrc = g_X8 + (size_t)(mBase + a_row) * DD + a_seg * 16;
    const uint8_t* bBase = g_C8 + (size_t)(cBase + b_row) * DD + b_seg * 16;
    const uint32_t aDst = sBase + (uint32_t)a_row * ROWB + a_seg * 16;
    const uint32_t bDst = sBase + A_BYTES + (uint32_t)b_row * ROWB + b_seg * 16;

    // ldmatrix lane->address maps (byte units; rows are 80B apart)
    const int aLdRow = lane & 15;
    const int aLdCol = 16 * (lane >> 4);
    const int bLdRow = (lane & 7) + ((lane >> 4) << 3);
    const int bLdCol = 16 * ((lane >> 3) & 1);

    const float NEG_INF = __int_as_float(0xff800000);
    float v0 = NEG_INF, v1 = NEG_INF, v2 = NEG_INF, v3 = NEG_INF;
    float v4 = NEG_INF, v5 = NEG_INF, v6 = NEG_INF, v7 = NEG_INF;
    int j0 = 0x7FFFFFFF, j1 = 0x7FFFFFFF, j2 = 0x7FFFFFFF, j3 = 0x7FFFFFFF;
    int j4 = 0x7FFFFFFF, j5 = 0x7FFFFFFF, j6 = 0x7FFFFFFF, j7 = 0x7FFFFFFF;

    const int q_scan = tid >> 2;                    // query row (0..63)
    const int l4     = tid & 3;                     // 32-col slice
    const int rot    = (q_scan + l4 * 8) & 31;

    // PF: prefetch slab G (chunk G/NKT, kt G%NKT) into buf G%3.
#define PF(G)                                                                 \
    do {                                                                      \
        uint32_t so = (uint32_t)((G) % NSTAGE) * STAGE_BYTES;                 \
        const uint8_t* as = aSrc + ((G) & (NKT - 1)) * 64;                    \
        const uint8_t* bs = bBase + (size_t)((G) >> 4) * (BN * DD)            \
                            + ((G) & (NKT - 1)) * 64;                         \
        CPA(aDst + so, as);                                                   \
        CPA(bDst + so, bs);                                                   \
        CPA(bDst + so + 16u, bs + 16);                                        \
        CP_COMMIT;                                                            \
    } while (0)

    PF(0);
    PF(1);

    float ac[2][4][4];
#pragma unroll
    for (int ma = 0; ma < 2; ++ma)
#pragma unroll
        for (int nb = 0; nb < 4; ++nb)
#pragma unroll
            for (int r = 0; r < 4; ++r) ac[ma][nb][r] = 0.f;

#pragma unroll 1
    for (int g = 0; g < TOTSLAB; ++g) {
        if (g < TOTSLAB - 1) { CP_WAIT1; } else { CP_WAIT0; }
        __syncthreads();                 // slab g ready; buf (g+2)%3 consumed
        if (g + 2 < TOTSLAB) PF(g + 2);

        const uint32_t sA = sBase + (uint32_t)(g % NSTAGE) * STAGE_BYTES;
        const uint32_t sB = sA + A_BYTES;
#pragma unroll
        for (int ks = 0; ks < 2; ++ks) {          // two k32 steps per 64B slab
            const int k0 = ks * 32;
            uint32_t af[2][4], bf[4][2];
#pragma unroll
            for (int ma = 0; ma < 2; ++ma)
                ldsm_x4(af[ma],
                        sA + (uint32_t)(wm + ma * 16 + aLdRow) * ROWB + k0 + aLdCol);
#pragma unroll
            for (int nq = 0; nq < 2; ++nq) {
                uint32_t t[4];
                ldsm_x4(t, sB + (uint32_t)(wn + nq * 16 + bLdRow) * ROWB + k0 + bLdCol);
                bf[nq * 2][0] = t[0]; bf[nq * 2][1] = t[1];
                bf[nq * 2 + 1][0] = t[2]; bf[nq * 2 + 1][1] = t[3];
            }
#pragma unroll
            for (int ma = 0; ma < 2; ++ma)
#pragma unroll
                for (int nb = 0; nb < 4; ++nb)
                    mma_fp8(ac[ma][nb], af[ma], bf[nb]);
        }

        if ((g & (NKT - 1)) == NKT - 1) {
            // ---- chunk epilogue (pipeline stays full: slabs g+1,g+2 in flight)
            const int nBase = (g >> 4) * BN;

            // Stage scores psi = 2*dot - c2 into Stg.
#pragma unroll
            for (int ma = 0; ma < 2; ++ma) {
                const int m0 = wm + ma * 16 + gid;
#pragma unroll
                for (int nb = 0; nb < 4; ++nb) {
                    const int n0 = wn + nb * 8 + 2 * tig;
                    const float cc0 = g_c2[cBase + nBase + n0];
                    const float cc1 = g_c2[cBase + nBase + n0 + 1];
                    Stg[m0 * BN + n0]           = fmaf(2.f, ac[ma][nb][0], -cc0);
                    Stg[m0 * BN + n0 + 1]       = fmaf(2.f, ac[ma][nb][1], -cc1);
                    Stg[(m0 + 8) * BN + n0]     = fmaf(2.f, ac[ma][nb][2], -cc0);
                    Stg[(m0 + 8) * BN + n0 + 1] = fmaf(2.f, ac[ma][nb][3], -cc1);
                }
            }
            __syncthreads();

            // Top-8 scan: 4 threads per query, 32 cols each (rotated).
            // (No trailing sync: next write to Stg is 16 slabs away, behind
            // multiple __syncthreads.)
#pragma unroll 1
            for (int j = 0; j < 32; ++j) {
                int jj  = (j + rot) & 31;
                int col = l4 * 32 + jj;
                float s = Stg[q_scan * BN + col];
                int   n = cBase + nBase + col;
                TRYINS(s, n)
            }

            // reset accumulators for next chunk
#pragma unroll
            for (int ma = 0; ma < 2; ++ma)
#pragma unroll
                for (int nb = 0; nb < 4; ++nb)
#pragma unroll
                    for (int r = 0; r < 4; ++r) ac[ma][nb][r] = 0.f;
        }
    }
#undef PF

    // Write top-6 candidate ids per (query, split, thread).
    int* dst = &g_cand[(size_t)(mBase + q_scan) * NCAND
                       + blockIdx.y * (4 * KKEEP) + l4 * KKEEP];
    dst[0] = j0; dst[1] = j1; dst[2] = j2;
    dst[3] = j3; dst[4] = j4; dst[5] = j5;
}

// ---------------------------------------------------------------------------
// Exact fp32 rescore of 96 candidates/query + top-8 + gather/mean.
// One warp per query; 8 queries per block.
__global__ void __launch_bounds__(256) rescore_kernel(const float* __restrict__ X,
                                                      const float* __restrict__ C,
                                                      float* __restrict__ out,
                                                      float* __restrict__ out_ids)
{
    __shared__ float sv[8][NCAND];
    __shared__ int   si[8][NCAND];
    __shared__ int   sel[8][KSEL];

    const int tid  = threadIdx.x;
    const int wid  = tid >> 5;
    const int lane = tid & 31;
    const int q    = blockIdx.x * 8 + wid;

    const float4* X4 = (const float4*)(X + (size_t)q * DD);
    float4 xr[8];
#pragma unroll
    for (int i = 0; i < 8; ++i) xr[i] = X4[i * 32 + lane];
    const float x2 = g_x2[q];

#pragma unroll 1
    for (int c = 0; c < NCAND; ++c) {
        const int id = g_cand[(size_t)q * NCAND + c];
        const float4* C4 = (const float4*)(C + (size_t)id * DD);
        float s = 0.f;
#pragma unroll
        for (int i = 0; i < 8; ++i) {
            float4 cv = C4[i * 32 + lane];
            s += xr[i].x * cv.x + xr[i].y * cv.y + xr[i].z * cv.z + xr[i].w * cv.w;
        }
#pragma unroll
        for (int o = 16; o > 0; o >>= 1) s += __shfl_xor_sync(0xffffffffu, s, o);
        if (lane == 0) {
            sv[wid][c] = -(fmaf(-2.f, s, x2) + g_c2[id]);   // reference formula order
            si[wid][c] = id;
        }
    }
    __syncwarp();

    if (lane == 0) {
        const float NEG_INF = __int_as_float(0xff800000);
        float v0 = NEG_INF, v1 = NEG_INF, v2 = NEG_INF, v3 = NEG_INF;
        float v4 = NEG_INF, v5 = NEG_INF, v6 = NEG_INF, v7 = NEG_INF;
        int j0 = 0x7FFFFFFF, j1 = 0x7FFFFFFF, j2 = 0x7FFFFFFF, j3 = 0x7FFFFFFF;
        int j4 = 0x7FFFFFFF, j5 = 0x7FFFFFFF, j6 = 0x7FFFFFFF, j7 = 0x7FFFFFFF;
#pragma unroll 1
        for (int c = 0; c < NCAND; ++c) {
            float s = sv[wid][c];
            int   n = si[wid][c];
            TRYINS(s, n)
        }
        sel[wid][0] = j0; sel[wid][1] = j1; sel[wid][2] = j2; sel[wid][3] = j3;
        sel[wid][4] = j4; sel[wid][5] = j5; sel[wid][6] = j6; sel[wid][7] = j7;
        if (out_ids) {
            float* o = out_ids + (size_t)q * KSEL;
            o[0] = (float)j0; o[1] = (float)j1; o[2] = (float)j2; o[3] = (float)j3;
            o[4] = (float)j4; o[5] = (float)j5; o[6] = (float)j6; o[7] = (float)j7;
        }
    }
    __syncwarp();

    const float4* P0 = (const float4*)(C + (size_t)sel[wid][0] * DD);
    const float4* P1 = (const float4*)(C + (size_t)sel[wid][1] * DD);
    const float4* P2 = (const float4*)(C + (size_t)sel[wid][2] * DD);
    const float4* P3 = (const float4*)(C + (size_t)sel[wid][3] * DD);
    const float4* P4 = (const float4*)(C + (size_t)sel[wid][4] * DD);
    const float4* P5 = (const float4*)(C + (size_t)sel[wid][5] * DD);
    const float4* P6 = (const float4*)(C + (size_t)sel[wid][6] * DD);
    const float4* P7 = (const float4*)(C + (size_t)sel[wid][7] * DD);
    float4* O4 = (float4*)(out + (size_t)q * DD);
#pragma unroll
    for (int i = 0; i < 8; ++i) {
        const int f = i * 32 + lane;
        float4 a0 = P0[f], a1 = P1[f], a2 = P2[f], a3 = P3[f];
        float4 a4 = P4[f], a5 = P5[f], a6 = P6[f], a7 = P7[f];
        float4 rr;
        rr.x = (a0.x + a1.x + a2.x + a3.x + a4.x + a5.x + a6.x + a7.x) * 0.125f;
        rr.y = (a0.y + a1.y + a2.y + a3.y + a4.y + a5.y + a6.y + a7.y) * 0.125f;
        rr.z = (a0.z + a1.z + a2.z + a3.z + a4.z + a5.z + a6.z + a7.z) * 0.125f;
        rr.w = (a0.w + a1.w + a2.w + a3.w + a4.w + a5.w + a6.w + a7.w) * 0.125f;
        O4[f] = rr;
    }
}

// ---------------------------------------------------------------------------
extern "C" void kernel_launch(void* const* d_in, const int* in_sizes, int n_in,
                              void* d_out, int out_size)
{
    const float* X = (const float*)d_in[0];   // inputs   [4,2048,1024] f32
    const float* C = (const float*)d_in[1];   // codebook [16384,1024] f32

    float* out     = (float*)d_out;
    float* out_ids = nullptr;
    if (out_size >= MQ * DD + MQ * KSEL)
        out_ids = out + (size_t)MQ * DD;

    cprep_kernel<<<NC / 8, 256>>>(C);   // e4m3 convert + c2 norms, one pass
    xprep_kernel<<<MQ / 8, 256>>>(X);   // e4m3 convert + x2 norms, one pass

    cudaFuncSetAttribute(shortlist_kernel,
                         cudaFuncAttributeMaxDynamicSharedMemorySize, SMEM_BYTES);
    dim3 grid(MQ / BM, NSPLIT);
    shortlist_kernel<<<grid, NT, SMEM_BYTES>>>();

    rescore_kernel<<<MQ / 8, 256>>>(X, C, out, out_ids);
}

// round 17
// speedup vs baseline: 1.1667x; 1.0772x over previous
#include <cuda_runtime.h>
#include <cuda_bf16.h>
#include <cuda_fp8.h>
#include <stdint.h>

// Problem dims
#define MQ    8192
#define DD    1024
#define NC    16384
#define KSEL  8
#define KKEEP 8                          // candidates kept per scan-thread
#define NCAND 64                         // 2 splits x 4 threads x 8

// FP8 shortlist tiling: 64 queries x 128-code chunks, warp tile 32x32,
// K-slab = 64 fp8 bytes, flattened slab pipeline (depth 2), occupancy 2.
#define BM 64
#define BN 128
#define NT 256
#define NSPLIT 2
#define CODES_PER_CTA (NC / NSPLIT)      // 8192
#define NCHUNK (CODES_PER_CTA / BN)      // 64
#define NKT    16                        // 1024 / 64
#define TOTSLAB (NCHUNK * NKT)           // 1024

#define ROWB   80u                       // 64 data bytes + 16 pad
#define A_BYTES (64u * ROWB)             // 5120
#define B_BYTES (128u * ROWB)            // 10240
#define STAGE_BYTES (A_BYTES + B_BYTES)  // 15360
#define NSTAGE 3
#define STG_OFF (NSTAGE * STAGE_BYTES)   // 46080
#define SMEM_BYTES (STG_OFF + BM * BN * 4)  // 78848

// ---------------------------------------------------------------------------
__device__ float    g_c2[NC];
__device__ float    g_x2[MQ];
__device__ uint8_t  g_X8[(size_t)MQ * DD];   // e4m3 queries  (8 MB)
__device__ uint8_t  g_C8[(size_t)NC * DD];   // e4m3 codebook (16 MB)
__device__ int      g_cand[(size_t)MQ * NCAND];

// ---------------------------------------------------------------------------
// Fused convert(e4m3) + squared-norm kernels: one warp per row, single pass.
__device__ __forceinline__ uint32_t pack_fp8x4(float4 v) {
    uint32_t b0 = __nv_cvt_float_to_fp8(v.x, __NV_SATFINITE, __NV_E4M3);
    uint32_t b1 = __nv_cvt_float_to_fp8(v.y, __NV_SATFINITE, __NV_E4M3);
    uint32_t b2 = __nv_cvt_float_to_fp8(v.z, __NV_SATFINITE, __NV_E4M3);
    uint32_t b3 = __nv_cvt_float_to_fp8(v.w, __NV_SATFINITE, __NV_E4M3);
    return b0 | (b1 << 8) | (b2 << 16) | (b3 << 24);
}

__global__ void cprep_kernel(const float* __restrict__ src) {
    int row = blockIdx.x * 8 + (threadIdx.x >> 5);
    if (row >= NC) return;
    int lane = threadIdx.x & 31;
    const float4* r4 = (const float4*)(src + (size_t)row * DD);
    uint32_t* dst = (uint32_t*)(g_C8 + (size_t)row * DD);
    float s = 0.f;
#pragma unroll
    for (int i = 0; i < 8; ++i) {
        float4 v = r4[i * 32 + lane];
        s += v.x * v.x + v.y * v.y + v.z * v.z + v.w * v.w;
        dst[i * 32 + lane] = pack_fp8x4(v);
    }
#pragma unroll
    for (int o = 16; o > 0; o >>= 1) s += __shfl_xor_sync(0xffffffffu, s, o);
    if (lane == 0) g_c2[row] = s;
}

__global__ void xprep_kernel(const float* __restrict__ src) {
    int row = blockIdx.x * 8 + (threadIdx.x >> 5);
    if (row >= MQ) return;
    int lane = threadIdx.x & 31;
    const float4* r4 = (const float4*)(src + (size_t)row * DD);
    uint32_t* dst = (uint32_t*)(g_X8 + (size_t)row * DD);
    float s = 0.f;
#pragma unroll
    for (int i = 0; i < 8; ++i) {
        float4 v = r4[i * 32 + lane];
        s += v.x * v.x + v.y * v.y + v.z * v.z + v.w * v.w;
        dst[i * 32 + lane] = pack_fp8x4(v);
    }
#pragma unroll
    for (int o = 16; o > 0; o >>= 1) s += __shfl_xor_sync(0xffffffffu, s, o);
    if (lane == 0) g_x2[row] = s;
}

// ---------------------------------------------------------------------------
// Scalar top-8 (value desc; ties -> smaller index first, matching JAX top_k)
#define BUBBLE(va, ia, vb, ib)                                    \
    if (va > vb || (va == vb && ia < ib)) {                       \
        float _tv = va; va = vb; vb = _tv;                        \
        int   _ti = ia; ia = ib; ib = _ti;                        \
    }
#define TRYINS(s, n)                                              \
    if ((s) > v7 || ((s) == v7 && (n) < j7)) {                    \
        v7 = (s); j7 = (n);                                       \
        BUBBLE(v7, j7, v6, j6)                                    \
        BUBBLE(v6, j6, v5, j5)                                    \
        BUBBLE(v5, j5, v4, j4)                                    \
        BUBBLE(v4, j4, v3, j3)                                    \
        BUBBLE(v3, j3, v2, j2)                                    \
        BUBBLE(v2, j2, v1, j1)                                    \
        BUBBLE(v1, j1, v0, j0)                                    \
    }

// ---------------------------------------------------------------------------
// PTX wrappers
__device__ __forceinline__ void ldsm_x4(uint32_t* r, uint32_t addr) {
    asm volatile("ldmatrix.sync.aligned.m8n8.x4.shared.b16 {%0,%1,%2,%3}, [%4];\n"
        : "=r"(r[0]), "=r"(r[1]), "=r"(r[2]), "=r"(r[3]) : "r"(addr));
}
__device__ __forceinline__ void mma_fp8(float* d, const uint32_t* a, const uint32_t* b) {
    asm volatile("mma.sync.aligned.m16n8k32.row.col.f32.e4m3.e4m3.f32 "
        "{%0,%1,%2,%3}, {%4,%5,%6,%7}, {%8,%9}, {%0,%1,%2,%3};\n"
        : "+f"(d[0]), "+f"(d[1]), "+f"(d[2]), "+f"(d[3])
        : "r"(a[0]), "r"(a[1]), "r"(a[2]), "r"(a[3]), "r"(b[0]), "r"(b[1]));
}
#define CPA(dst, src) \
    asm volatile("cp.async.cg.shared.global [%0], [%1], 16;\n" :: "r"(dst), "l"(src))
#define CP_COMMIT asm volatile("cp.async.commit_group;\n" ::)
#define CP_WAIT1  asm volatile("cp.async.wait_group 1;\n" ::)
#define CP_WAIT0  asm volatile("cp.async.wait_group 0;\n" ::)

// ---------------------------------------------------------------------------
// Shortlist kernel: e4m3 mma.sync GEMM (score = 2*xc - c2) + per-thread top-8.
// Flattened slab pipeline (depth 2, NSTAGE 3), occupancy 2.
__global__ void __launch_bounds__(NT, 2) shortlist_kernel() {
    extern __shared__ __align__(128) unsigned char sraw[];
    float* Stg = (float*)(sraw + STG_OFF);

    const int tid  = threadIdx.x;
    const int lane = tid & 31;
    const int wid  = tid >> 5;
    const int wm   = (wid >> 2) * 32;               // warp m-origin: 0,32
    const int wn   = (wid & 3) * 32;                // warp n-origin: 0,32,64,96
    const int gid  = lane >> 2;
    const int tig  = lane & 3;
    const int mBase = blockIdx.x * BM;
    const int cBase = blockIdx.y * CODES_PER_CTA;

    const uint32_t sBase = (uint32_t)__cvta_generic_to_shared(sraw);

    // cp.async decomposition: A 64 rows x 4 segs (1/thread), B 128 rows x 4 segs (2/thread)
    const int a_row = tid >> 2, a_seg = tid & 3;
    const int b_row = tid >> 1, b_seg = (tid & 1) * 2;
    const uint8_t* aSrc = g_X8 + (size_t)(mBase + a_row) * DD + a_seg * 16;
    const uint8_t* bBase = g_C8 + (size_t)(cBase + b_row) * DD + b_seg * 16;
    const uint32_t aDst = sBase + (uint32_t)a_row * ROWB + a_seg * 16;
    const uint32_t bDst = sBase + A_BYTES + (uint32_t)b_row * ROWB + b_seg * 16;

    // ldmatrix lane->address maps (byte units; rows are 80B apart)
    const int aLdRow = lane & 15;
    const int aLdCol = 16 * (lane >> 4);
    const int bLdRow = (lane & 7) + ((lane >> 4) << 3);
    const int bLdCol = 16 * ((lane >> 3) & 1);

    const float NEG_INF = __int_as_float(0xff800000);
    float v0 = NEG_INF, v1 = NEG_INF, v2 = NEG_INF, v3 = NEG_INF;
    float v4 = NEG_INF, v5 = NEG_INF, v6 = NEG_INF, v7 = NEG_INF;
    int j0 = 0x7FFFFFFF, j1 = 0x7FFFFFFF, j2 = 0x7FFFFFFF, j3 = 0x7FFFFFFF;
    int j4 = 0x7FFFFFFF, j5 = 0x7FFFFFFF, j6 = 0x7FFFFFFF, j7 = 0x7FFFFFFF;

    const int q_scan = tid >> 2;                    // query row (0..63)
    const int l4     = tid & 3;                     // 32-col slice
    const int rot    = (q_scan + l4 * 8) & 31;

    // PF: prefetch slab G (chunk G/NKT, kt G%NKT) into buf G%3.
#define PF(G)                                                                 \
    do {                                                                      \
        uint32_t so = (uint32_t)((G) % NSTAGE) * STAGE_BYTES;                 \
        const uint8_t* as = aSrc + ((G) & (NKT - 1)) * 64;                    \
        const uint8_t* bs = bBase + (size_t)((G) >> 4) * (BN * DD)            \
                            + ((G) & (NKT - 1)) * 64;                         \
        CPA(aDst + so, as);                                                   \
        CPA(bDst + so, bs);                                                   \
        CPA(bDst + so + 16u, bs + 16);                                        \
        CP_COMMIT;                                                            \
    } while (0)

    PF(0);
    PF(1);

    float ac[2][4][4];
#pragma unroll
    for (int ma = 0; ma < 2; ++ma)
#pragma unroll
        for (int nb = 0; nb < 4; ++nb)
#pragma unroll
            for (int r = 0; r < 4; ++r) ac[ma][nb][r] = 0.f;

#pragma unroll 1
    for (int g = 0; g < TOTSLAB; ++g) {
        if (g < TOTSLAB - 1) { CP_WAIT1; } else { CP_WAIT0; }
        __syncthreads();                 // slab g ready; buf (g+2)%3 consumed
        if (g + 2 < TOTSLAB) PF(g + 2);

        const uint32_t sA = sBase + (uint32_t)(g % NSTAGE) * STAGE_BYTES;
        const uint32_t sB = sA + A_BYTES;
#pragma unroll
        for (int ks = 0; ks < 2; ++ks) {          // two k32 steps per 64B slab
            const int k0 = ks * 32;
            uint32_t af[2][4], bf[4][2];
#pragma unroll
            for (int ma = 0; ma < 2; ++ma)
                ldsm_x4(af[ma],
                        sA + (uint32_t)(wm + ma * 16 + aLdRow) * ROWB + k0 + aLdCol);
#pragma unroll
            for (int nq = 0; nq < 2; ++nq) {
                uint32_t t[4];
                ldsm_x4(t, sB + (uint32_t)(wn + nq * 16 + bLdRow) * ROWB + k0 + bLdCol);
                bf[nq * 2][0] = t[0]; bf[nq * 2][1] = t[1];
                bf[nq * 2 + 1][0] = t[2]; bf[nq * 2 + 1][1] = t[3];
            }
#pragma unroll
            for (int ma = 0; ma < 2; ++ma)
#pragma unroll
                for (int nb = 0; nb < 4; ++nb)
                    mma_fp8(ac[ma][nb], af[ma], bf[nb]);
        }

        if ((g & (NKT - 1)) == NKT - 1) {
            // ---- chunk epilogue (pipeline stays full: slabs g+1,g+2 in flight)
            const int nBase = (g >> 4) * BN;

            // Stage scores psi = 2*dot - c2 into Stg.
#pragma unroll
            for (int ma = 0; ma < 2; ++ma) {
                const int m0 = wm + ma * 16 + gid;
#pragma unroll
                for (int nb = 0; nb < 4; ++nb) {
                    const int n0 = wn + nb * 8 + 2 * tig;
                    const float cc0 = g_c2[cBase + nBase + n0];
                    const float cc1 = g_c2[cBase + nBase + n0 + 1];
                    Stg[m0 * BN + n0]           = fmaf(2.f, ac[ma][nb][0], -cc0);
                    Stg[m0 * BN + n0 + 1]       = fmaf(2.f, ac[ma][nb][1], -cc1);
                    Stg[(m0 + 8) * BN + n0]     = fmaf(2.f, ac[ma][nb][2], -cc0);
                    Stg[(m0 + 8) * BN + n0 + 1] = fmaf(2.f, ac[ma][nb][3], -cc1);
                }
            }
            __syncthreads();

            // Top-8 scan: 4 threads per query, 32 cols each (rotated).
            // (No trailing sync: next write to Stg is 16 slabs away, behind
            // multiple __syncthreads.)
#pragma unroll 1
            for (int j = 0; j < 32; ++j) {
                int jj  = (j + rot) & 31;
                int col = l4 * 32 + jj;
                float s = Stg[q_scan * BN + col];
                int   n = cBase + nBase + col;
                TRYINS(s, n)
            }

            // reset accumulators for next chunk
#pragma unroll
            for (int ma = 0; ma < 2; ++ma)
#pragma unroll
                for (int nb = 0; nb < 4; ++nb)
#pragma unroll
                    for (int r = 0; r < 4; ++r) ac[ma][nb][r] = 0.f;
        }
    }
#undef PF

    // Write top-8 candidate ids per (query, split, thread).
    int* dst = &g_cand[(size_t)(mBase + q_scan) * NCAND
                       + blockIdx.y * (4 * KKEEP) + l4 * KKEEP];
    dst[0] = j0; dst[1] = j1; dst[2] = j2; dst[3] = j3;
    dst[4] = j4; dst[5] = j5; dst[6] = j6; dst[7] = j7;
}

// ---------------------------------------------------------------------------
// Exact fp32 rescore of 64 candidates/query + top-8 + gather/mean.
// One warp per query; 8 queries per block.
__global__ void __launch_bounds__(256) rescore_kernel(const float* __restrict__ X,
                                                      const float* __restrict__ C,
                                                      float* __restrict__ out,
                                                      float* __restrict__ out_ids)
{
    __shared__ float sv[8][NCAND];
    __shared__ int   si[8][NCAND];
    __shared__ int   sel[8][KSEL];

    const int tid  = threadIdx.x;
    const int wid  = tid >> 5;
    const int lane = tid & 31;
    const int q    = blockIdx.x * 8 + wid;

    const float4* X4 = (const float4*)(X + (size_t)q * DD);
    float4 xr[8];
#pragma unroll
    for (int i = 0; i < 8; ++i) xr[i] = X4[i * 32 + lane];
    const float x2 = g_x2[q];

#pragma unroll 1
    for (int c = 0; c < NCAND; ++c) {
        const int id = g_cand[(size_t)q * NCAND + c];
        const float4* C4 = (const float4*)(C + (size_t)id * DD);
        float s = 0.f;
#pragma unroll
        for (int i = 0; i < 8; ++i) {
            float4 cv = C4[i * 32 + lane];
            s += xr[i].x * cv.x + xr[i].y * cv.y + xr[i].z * cv.z + xr[i].w * cv.w;
        }
#pragma unroll
        for (int o = 16; o > 0; o >>= 1) s += __shfl_xor_sync(0xffffffffu, s, o);
        if (lane == 0) {
            sv[wid][c] = -(fmaf(-2.f, s, x2) + g_c2[id]);   // reference formula order
            si[wid][c] = id;
        }
    }
    __syncwarp();

    if (lane == 0) {
        const float NEG_INF = __int_as_float(0xff800000);
        float v0 = NEG_INF, v1 = NEG_INF, v2 = NEG_INF, v3 = NEG_INF;
        float v4 = NEG_INF, v5 = NEG_INF, v6 = NEG_INF, v7 = NEG_INF;
        int j0 = 0x7FFFFFFF, j1 = 0x7FFFFFFF, j2 = 0x7FFFFFFF, j3 = 0x7FFFFFFF;
        int j4 = 0x7FFFFFFF, j5 = 0x7FFFFFFF, j6 = 0x7FFFFFFF, j7 = 0x7FFFFFFF;
#pragma unroll 1
        for (int c = 0; c < NCAND; ++c) {
            float s = sv[wid][c];
            int   n = si[wid][c];
            TRYINS(s, n)
        }
        sel[wid][0] = j0; sel[wid][1] = j1; sel[wid][2] = j2; sel[wid][3] = j3;
        sel[wid][4] = j4; sel[wid][5] = j5; sel[wid][6] = j6; sel[wid][7] = j7;
        if (out_ids) {
            float* o = out_ids + (size_t)q * KSEL;
            o[0] = (float)j0; o[1] = (float)j1; o[2] = (float)j2; o[3] = (float)j3;
            o[4] = (float)j4; o[5] = (float)j5; o[6] = (float)j6; o[7] = (float)j7;
        }
    }
    __syncwarp();

    const float4* P0 = (const float4*)(C + (size_t)sel[wid][0] * DD);
    const float4* P1 = (const float4*)(C + (size_t)sel[wid][1] * DD);
    const float4* P2 = (const float4*)(C + (size_t)sel[wid][2] * DD);
    const float4* P3 = (const float4*)(C + (size_t)sel[wid][3] * DD);
    const float4* P4 = (const float4*)(C + (size_t)sel[wid][4] * DD);
    const float4* P5 = (const float4*)(C + (size_t)sel[wid][5] * DD);
    const float4* P6 = (const float4*)(C + (size_t)sel[wid][6] * DD);
    const float4* P7 = (const float4*)(C + (size_t)sel[wid][7] * DD);
    float4* O4 = (float4*)(out + (size_t)q * DD);
#pragma unroll
    for (int i = 0; i < 8; ++i) {
        const int f = i * 32 + lane;
        float4 a0 = P0[f], a1 = P1[f], a2 = P2[f], a3 = P3[f];
        float4 a4 = P4[f], a5 = P5[f], a6 = P6[f], a7 = P7[f];
        float4 rr;
        rr.x = (a0.x + a1.x + a2.x + a3.x + a4.x + a5.x + a6.x + a7.x) * 0.125f;
        rr.y = (a0.y + a1.y + a2.y + a3.y + a4.y + a5.y + a6.y + a7.y) * 0.125f;
        rr.z = (a0.z + a1.z + a2.z + a3.z + a4.z + a5.z + a6.z + a7.z) * 0.125f;
        rr.w = (a0.w + a1.w + a2.w + a3.w + a4.w + a5.w + a6.w + a7.w) * 0.125f;
        O4[f] = rr;
    }
}

// ---------------------------------------------------------------------------
extern "C" void kernel_launch(void* const* d_in, const int* in_sizes, int n_in,
                              void* d_out, int out_size)
{
    const float* X = (const float*)d_in[0];   // inputs   [4,2048,1024] f32
    const float* C = (const float*)d_in[1];   // codebook [16384,1024] f32

    float* out     = (float*)d_out;
    float* out_ids = nullptr;
    if (out_size >= MQ * DD + MQ * KSEL)
        out_ids = out + (size_t)MQ * DD;

    cprep_kernel<<<NC / 8, 256>>>(C);   // e4m3 convert + c2 norms, one pass
    xprep_kernel<<<MQ / 8, 256>>>(X);   // e4m3 convert + x2 norms, one pass

    cudaFuncSetAttribute(shortlist_kernel,
                         cudaFuncAttributeMaxDynamicSharedMemorySize, SMEM_BYTES);
    dim3 grid(MQ / BM, NSPLIT);
    shortlist_kernel<<<grid, NT, SMEM_BYTES>>>();

    rescore_kernel<<<MQ / 8, 256>>>(X, C, out, out_ids);
}